// round 12
// baseline (speedup 1.0000x reference)
#include <cuda_runtime.h>

// ChamferDistance: B=8, N=M=8192, D=3.
// d(i,j) = n_j + (-2y_j).x_i + |x_i|^2 ; min over j per i (both directions).
// R7 inner loop (owned coords broadcast into both f32x2 lanes, opposing points
// pair-packed in shared with -2 folded in; scalar FMNMX mins).
// 296 persistent blocks (exactly 2/SM), static round-robin over 2048 fine
// units (64 groups x 32 j-slices) -> ~1.2% SM imbalance. Single launch.

#define TPB     256
#define RX      8
#define CHUNK   (TPB * RX)          // 2048 owned points per group
#define PTS     8192
#define BATCH   8
#define NCHUNK  (PTS / CHUNK)       // 4
#define NJS     32                  // j-slices per group
#define JSEG    (PTS / NJS)         // 256 opposing points per unit
#define JP      (JSEG / 2)          // 128 j-pairs per tile
#define NGROUP  (2 * BATCH * NCHUNK)    // 64
#define NUNITS  (NGROUP * NJS)          // 2048
#define GRID    296                     // 2 blocks per SM exactly

__device__ float    g_pmin[NGROUP * NJS * CHUNK];   // 16.8 MB scratch
__device__ float    g_part[NGROUP];
__device__ unsigned g_gticket[NGROUP];
__device__ unsigned g_fticket;

#define PACK_F32X2(out, lo, hi) \
    asm("mov.b64 %0, {%1, %2};" : "=l"(out) : "f"(lo), "f"(hi))

#define UNPACK_F32X2(lo, hi, in) \
    asm("mov.b64 {%0, %1}, %2;" : "=f"(lo), "=f"(hi) : "l"(in))

#define FMA_F32X2(d, a, b, c) \
    asm("fma.rn.f32x2 %0, %1, %2, %3;" : "=l"(d) : "l"(a), "l"(b), "l"(c))

__global__ __launch_bounds__(TPB)
void chamfer_pass_kernel(const float* __restrict__ x, const float* __restrict__ y,
                         float* __restrict__ out) {
    // Per j-pair: sAB = {(-2a0,-2a1),(-2b0,-2b1)}, sCN = {(-2c0,-2c1),(n0,n1)}
    __shared__ __align__(16) ulonglong2 sAB[JP];
    __shared__ __align__(16) ulonglong2 sCN[JP];
    __shared__ float red[TPB];
    __shared__ bool  isComb, isFin;

    const int tid = threadIdx.x;

    for (int u = blockIdx.x; u < NUNITS; u += GRID) {
        const int group = u >> 5;           // 0..63
        const int js    = u & (NJS - 1);    // 0..31
        const int dir   = group >> 5;       // 0..1
        const int batch = (group >> 2) & 7; // 0..7
        const int chunk = group & 3;        // 0..3

        const float* __restrict__ ownb = (dir ? y : x) + (size_t)batch * PTS * 3;
        const float* __restrict__ oppb = (dir ? x : y) + (size_t)batch * PTS * 3;

        // owned points: coord broadcast into both lanes
        unsigned long long xa[RX], xb[RX], xc[RX];
        float x0[RX], x1[RX], x2[RX], mnl[RX], mnh[RX];
#pragma unroll
        for (int r = 0; r < RX; r++) {
            int i = chunk * CHUNK + r * TPB + tid;
            x0[r] = ownb[i * 3 + 0];
            x1[r] = ownb[i * 3 + 1];
            x2[r] = ownb[i * 3 + 2];
            PACK_F32X2(xa[r], x0[r], x0[r]);
            PACK_F32X2(xb[r], x1[r], x1[r]);
            PACK_F32X2(xc[r], x2[r], x2[r]);
            mnl[r] = 3.4e38f;
            mnh[r] = 3.4e38f;
        }

        __syncthreads();   // protect previous unit's tile
        if (tid < JSEG) {
            const float* p = oppb + (size_t)(js * JSEG + tid) * 3;
            float a = p[0], b = p[1], c = p[2];
            float n = fmaf(a, a, fmaf(b, b, c * c));
            int jp = tid >> 1, lane = tid & 1;
            float* pab = (float*)&sAB[jp];
            float* pcn = (float*)&sCN[jp];
            pab[lane + 0] = -2.0f * a;
            pab[lane + 2] = -2.0f * b;
            pcn[lane + 0] = -2.0f * c;
            pcn[lane + 2] = n;
        }
        __syncthreads();

#pragma unroll 8
        for (int jp = 0; jp < JP; ++jp) {
            ulonglong2 ab = sAB[jp];   // LDS.128 broadcast
            ulonglong2 cn = sCN[jp];   // LDS.128 broadcast
#pragma unroll
            for (int r = 0; r < RX; ++r) {
                unsigned long long t;
                FMA_F32X2(t, xc[r], cn.x, cn.y);
                FMA_F32X2(t, xb[r], ab.y, t);
                FMA_F32X2(t, xa[r], ab.x, t);
                float lo, hi;
                UNPACK_F32X2(lo, hi, t);
                mnl[r] = fminf(mnl[r], lo);
                mnh[r] = fminf(mnh[r], hi);
            }
        }

        // publish partial mins for this (group, js)
#pragma unroll
        for (int r = 0; r < RX; r++)
            g_pmin[(group * NJS + js) * CHUNK + r * TPB + tid] = fminf(mnl[r], mnh[r]);

        // group ticket: 32nd arrival combines (fixed order -> deterministic)
        __threadfence();
        __syncthreads();
        if (tid == 0) {
            unsigned t = atomicAdd(&g_gticket[group], 1u);
            isComb = (t == NJS - 1);
            if (isComb) g_gticket[group] = 0;   // reset for next replay
        }
        __syncthreads();
        if (isComb) {
            __threadfence();
            float s = 0.0f;
#pragma unroll
            for (int r = 0; r < RX; r++) {
                int idx = r * TPB + tid;
                float m = 3.4e38f;
#pragma unroll 8
                for (int ss = 0; ss < NJS; ss++)
                    m = fminf(m, g_pmin[(group * NJS + ss) * CHUNK + idx]);
                s += m + fmaf(x0[r], x0[r], fmaf(x1[r], x1[r], x2[r] * x2[r]));
            }
            red[tid] = s;
            __syncthreads();
#pragma unroll
            for (int o = TPB / 2; o > 0; o >>= 1) {
                if (tid < o) red[tid] += red[tid + o];
                __syncthreads();
            }
            if (tid == 0) g_part[group] = red[0];

            // global ticket: 64th combiner reduces the scalar
            __threadfence();
            __syncthreads();
            if (tid == 0) {
                unsigned t = atomicAdd(&g_fticket, 1u);
                isFin = (t == NGROUP - 1);
                if (isFin) g_fticket = 0;   // reset for next replay
            }
            __syncthreads();
            if (isFin) {
                __threadfence();
                float v = (tid < NGROUP) ? g_part[tid] : 0.0f;
                red[tid] = v;
                __syncthreads();
#pragma unroll
                for (int o = TPB / 2; o > 0; o >>= 1) {
                    if (tid < o) red[tid] += red[tid + o];
                    __syncthreads();
                }
                if (tid == 0) out[0] = red[0] * (1.0f / 65536.0f);
            }
        }
    }
}

extern "C" void kernel_launch(void* const* d_in, const int* in_sizes, int n_in,
                              void* d_out, int out_size) {
    const float* x = (const float*)d_in[0];
    const float* y = (const float*)d_in[1];
    float* out = (float*)d_out;

    chamfer_pass_kernel<<<GRID, TPB>>>(x, y, out);
}

// round 13
// speedup vs baseline: 1.2735x; 1.2735x over previous
#include <cuda_runtime.h>

// ChamferDistance: B=8, N=M=8192, D=3.
// d(i,j) = n_j + (-2x_i).y_j + |x_i|^2 ; min over j per i (both directions).
// Transposed packing (two owned pts per f32x2 reg, coords pre-scaled by -2;
// opposing point broadcast into both lanes in the shared tile).
// RX=4 (low regs) x NJS=8 -> 1024 blocks / 262K threads -> ~75% occupancy.
// Deterministic ticket-gated combines. Single kernel launch.

#define TPB     256
#define RX      4
#define NPK     (RX / 2)            // 2 packed owned pairs per thread
#define CHUNK   (TPB * RX)          // 1024 owned points per group
#define PTS     8192
#define BATCH   8
#define NCHUNK  (PTS / CHUNK)       // 8
#define NJS     8                   // j-slices per group
#define JSEG    (PTS / NJS)         // 1024 opposing points per block
#define TILE    JSEG
#define NGROUP  (2 * BATCH * NCHUNK)    // 128
#define NBLOCKS (NGROUP * NJS)          // 1024

__device__ float    g_pmin[NGROUP * NJS * CHUNK];   // 4.2 MB scratch
__device__ float    g_part[NGROUP];
__device__ unsigned g_gticket[NGROUP];
__device__ unsigned g_fticket;

#define PACK_F32X2(out, lo, hi) \
    asm("mov.b64 %0, {%1, %2};" : "=l"(out) : "f"(lo), "f"(hi))

#define UNPACK_F32X2(lo, hi, in) \
    asm("mov.b64 {%0, %1}, %2;" : "=f"(lo), "=f"(hi) : "l"(in))

#define FMA_F32X2(d, a, b, c) \
    asm("fma.rn.f32x2 %0, %1, %2, %3;" : "=l"(d) : "l"(a), "l"(b), "l"(c))

__global__ __launch_bounds__(TPB)
void chamfer_pass_kernel(const float* __restrict__ x, const float* __restrict__ y,
                         float* __restrict__ out) {
    const int bid   = blockIdx.x;
    const int dir   = bid >> 9;                 // 0..1
    const int batch = (bid >> 6) & 7;           // 0..7
    const int chunk = (bid >> 3) & 7;           // 0..7
    const int js    = bid & 7;                  // 0..7
    const int group = (dir * BATCH + batch) * NCHUNK + chunk;   // 0..127

    const float* __restrict__ ownb = (dir ? y : x) + (size_t)batch * PTS * 3;
    const float* __restrict__ oppb = (dir ? x : y) + (size_t)batch * PTS * 3;

    // Per opposing point j: sAB[j] = {(a,a),(b,b)}, sCN[j] = {(c,c),(n,n)}
    __shared__ __align__(16) ulonglong2 sAB[TILE];
    __shared__ __align__(16) ulonglong2 sCN[TILE];

    const int tid = threadIdx.x;

    // Owned points: two points per packed register, coords pre-scaled by -2.
    unsigned long long xa2[NPK], xb2[NPK], xc2[NPK];
    float mn[RX];
#pragma unroll
    for (int p = 0; p < NPK; p++) {
        int i0 = chunk * CHUNK + (2 * p)     * TPB + tid;
        int i1 = chunk * CHUNK + (2 * p + 1) * TPB + tid;
        PACK_F32X2(xa2[p], -2.0f * ownb[i0 * 3 + 0], -2.0f * ownb[i1 * 3 + 0]);
        PACK_F32X2(xb2[p], -2.0f * ownb[i0 * 3 + 1], -2.0f * ownb[i1 * 3 + 1]);
        PACK_F32X2(xc2[p], -2.0f * ownb[i0 * 3 + 2], -2.0f * ownb[i1 * 3 + 2]);
    }
#pragma unroll
    for (int r = 0; r < RX; r++) mn[r] = 3.4e38f;

    // single tile fill: JSEG == TILE
    {
        const int jbase = js * JSEG;
#pragma unroll
        for (int jj = tid; jj < TILE; jj += TPB) {
            const float* pp = oppb + (size_t)(jbase + jj) * 3;
            float a = pp[0], b = pp[1], c = pp[2];
            float n = fmaf(a, a, fmaf(b, b, c * c));
            ulonglong2 v0, v1;
            PACK_F32X2(v0.x, a, a);
            PACK_F32X2(v0.y, b, b);
            PACK_F32X2(v1.x, c, c);
            PACK_F32X2(v1.y, n, n);
            sAB[jj] = v0;
            sCN[jj] = v1;
        }
        __syncthreads();

#pragma unroll 4
        for (int j = 0; j < TILE; ++j) {
            ulonglong2 ab = sAB[j];   // LDS.128 broadcast: (a,a),(b,b)
            ulonglong2 cn = sCN[j];   // LDS.128 broadcast: (c,c),(n,n)
#pragma unroll
            for (int p = 0; p < NPK; ++p) {
                unsigned long long t;
                FMA_F32X2(t, xc2[p], cn.x, cn.y);   // (-2c_i)c_j + n_j
                FMA_F32X2(t, xb2[p], ab.y, t);
                FMA_F32X2(t, xa2[p], ab.x, t);
                float lo, hi;
                UNPACK_F32X2(lo, hi, t);
                mn[2 * p]     = fminf(mn[2 * p],     lo);
                mn[2 * p + 1] = fminf(mn[2 * p + 1], hi);
            }
        }
    }

    // publish this j-slice's partial mins (mn[r] belongs to point r*TPB+tid)
#pragma unroll
    for (int r = 0; r < RX; r++)
        g_pmin[(group * NJS + js) * CHUNK + r * TPB + tid] = mn[r];

    // per-group ticket: 8th arrival combines (fixed order -> deterministic)
    __shared__ bool isComb;
    __threadfence();
    __syncthreads();
    if (tid == 0) {
        unsigned t = atomicAdd(&g_gticket[group], 1u);
        isComb = (t == NJS - 1);
        if (isComb) g_gticket[group] = 0;   // reset for next replay
    }
    __syncthreads();
    if (!isComb) return;
    __threadfence();

    float s = 0.0f;
#pragma unroll
    for (int p = 0; p < NPK; p++) {
        float a0, a1, b0, b1, c0, c1;
        UNPACK_F32X2(a0, a1, xa2[p]);   // = -2 * coord
        UNPACK_F32X2(b0, b1, xb2[p]);
        UNPACK_F32X2(c0, c1, xc2[p]);
        float n0 = 0.25f * fmaf(a0, a0, fmaf(b0, b0, c0 * c0));
        float n1 = 0.25f * fmaf(a1, a1, fmaf(b1, b1, c1 * c1));
#pragma unroll
        for (int h = 0; h < 2; h++) {
            int r = 2 * p + h;
            int idx = r * TPB + tid;
            float m = 3.4e38f;
#pragma unroll
            for (int ss = 0; ss < NJS; ss++)
                m = fminf(m, g_pmin[(group * NJS + ss) * CHUNK + idx]);
            s += m + (h ? n1 : n0);
        }
    }

    __shared__ float red[TPB];
    red[tid] = s;
    __syncthreads();
#pragma unroll
    for (int o = TPB / 2; o > 0; o >>= 1) {
        if (tid < o) red[tid] += red[tid + o];
        __syncthreads();
    }
    if (tid == 0) g_part[group] = red[0];

    // global ticket over the 128 combiners: last one reduces the scalar
    __shared__ bool isFin;
    __threadfence();
    __syncthreads();
    if (tid == 0) {
        unsigned t = atomicAdd(&g_fticket, 1u);
        isFin = (t == NGROUP - 1);
        if (isFin) g_fticket = 0;   // reset for next replay
    }
    __syncthreads();
    if (!isFin) return;
    __threadfence();

    float v = (tid < NGROUP) ? g_part[tid] : 0.0f;
    red[tid] = v;
    __syncthreads();
#pragma unroll
    for (int o = TPB / 2; o > 0; o >>= 1) {
        if (tid < o) red[tid] += red[tid + o];
        __syncthreads();
    }
    if (tid == 0) out[0] = red[0] * (1.0f / 65536.0f);
}

extern "C" void kernel_launch(void* const* d_in, const int* in_sizes, int n_in,
                              void* d_out, int out_size) {
    const float* x = (const float*)d_in[0];
    const float* y = (const float*)d_in[1];
    float* out = (float*)d_out;

    chamfer_pass_kernel<<<NBLOCKS, TPB>>>(x, y, out);
}